// round 7
// baseline (speedup 1.0000x reference)
#include <cuda_runtime.h>
#include <math.h>

#define NB 512
#define FDIM 4096
#define DEG 3
#define ROWS_PER_CTA 8
#define NTHREADS 512
#define BATCH 8192
#define PSTRIDE 4608   // per-degree perm stride (elements, worst case 4096+512 pads)

// CSR of inverted hash tables (built once per launch, deterministic).
// perm entry (u16): feature(13 bits, 4096 = zero-pad slot) | sign<<15 (1 -> +x)
// g_off: per-bucket start offsets in u32 units (lists padded to even length)
__device__ __align__(16) unsigned short g_perm[DEG * PSTRIDE];
__device__ __align__(16) unsigned short g_off[DEG * (NB + 1)];

// ---------------------------------------------------------------------------
// Prologue: invert hash tables into per-bucket CSR, parallel + deterministic.
// 12 warp-tasks = (degree, quarter). Stable order: quarter-major, then
// feature order within each warp chunk via __match_any ranking.
// ---------------------------------------------------------------------------
__global__ void __launch_bounds__(NTHREADS)
build_csr(const int* __restrict__ idxh, const int* __restrict__ bith)
{
    __shared__ int hist[12][NB];      // per (deg,quarter) histogram -> cursors
    __shared__ int pc[NB];
    __shared__ int sc[2][NB];
    __shared__ int ebase[DEG][NB];    // exclusive element offsets
    const int t = threadIdx.x;
    const int w = t >> 5, lane = t & 31;

    for (int i = t; i < 12 * NB; i += NTHREADS) ((int*)hist)[i] = 0;
    __syncthreads();

    if (w < 12) {
        const int d = w >> 2, q = w & 3;
        const int base = d * FDIM + q * 1024;
        for (int it = 0; it < 32; it++) {
            int b = idxh[base + it * 32 + lane];
            atomicAdd(&hist[w][b], 1);
        }
    }
    __syncthreads();

    // pre-fill perm with pad entries (f=4096 -> reads zero slot, sign 0)
    for (int i = t; i < DEG * PSTRIDE; i += NTHREADS) g_perm[i] = 0x1000;

    for (int d = 0; d < DEG; d++) {
        int c = hist[d * 4 + 0][t] + hist[d * 4 + 1][t] +
                hist[d * 4 + 2][t] + hist[d * 4 + 3][t];
        pc[t] = c + (c & 1);                    // pad to even
        __syncthreads();
        int* s = sc[0]; int* dd = sc[1];
        s[t] = pc[t]; __syncthreads();
        for (int off = 1; off < NB; off <<= 1) {
            int v = s[t];
            if (t >= off) v += s[t - off];
            dd[t] = v;
            int* tmp = s; s = dd; dd = tmp;
            __syncthreads();
        }
        int excl = (t == 0) ? 0 : s[t - 1];
        ebase[d][t] = excl;
        g_off[d * (NB + 1) + t] = (unsigned short)(excl >> 1);
        if (t == NB - 1) g_off[d * (NB + 1) + NB] = (unsigned short)(s[NB - 1] >> 1);
        __syncthreads();
    }

    // convert histograms into per-(deg,quarter) element write cursors
    {
        for (int d = 0; d < DEG; d++) {
            int base = ebase[d][t];
            for (int q = 0; q < 4; q++) {
                int tmp = hist[d * 4 + q][t];
                hist[d * 4 + q][t] = base;
                base += tmp;
            }
        }
    }
    __syncthreads();

    if (w < 12) {
        const int d = w >> 2, q = w & 3;
        const int fbase = q * 1024;
        for (int it = 0; it < 32; it++) {
            int f  = fbase + it * 32 + lane;
            int b  = idxh[d * FDIM + f];
            int sg = bith[d * FDIM + f];
            unsigned m = __match_any_sync(0xffffffffu, b);
            int rank = __popc(m & ((1u << lane) - 1));
            int grp  = __popc(m);
            int base = hist[w][b];
            g_perm[d * PSTRIDE + base + rank] = (unsigned short)(f | (sg << 15));
            if (rank == grp - 1) hist[w][b] = base + grp;
            __syncwarp();
        }
    }
}

// ---------------------------------------------------------------------------
// Main kernel. Rows processed in pairs (r0,r1):
//  - X staged interleaved as float2 -> one LDS.64 feeds both rows
//  - gather count-sketch (no atomics), 3 degrees, both rows at once
//  - forward: 3 packed FFT-512, pack = s_d(r0) + i*s_d(r1) (1.5 waves)
//  - Hermitian split + spectral product -> P per row (k<=256)
//  - per 4 rows: packed inverse wave (2 FFT-512)
// ---------------------------------------------------------------------------
#define OFF_PERM   0          // 27648 (3*4608 u16)
#define OFF_OFF    27648      // 3078 -> pad to 3080
#define OFF_X2     30728      // 4097 float2 = 32776
#define OFF_REA    63504      // [2][512] f32 = 4096
#define OFF_IMA    67600
#define OFF_REB    71696
#define OFF_IMB    75792
#define OFF_S2     79888      // 1024 f32 (deg-2 pair stash: [re512|im512])
#define OFF_T      83984      // Tre[2][257], Tim[2][257] = 4112
#define OFF_P      88096      // Pre[4][257], Pim[4][257] = 8224
#define OFF_W      96320      // Wre[256], Wim[256] = 2048
#define SMEM_BYTES 98368

__device__ __forceinline__ void fft_stage(const float* __restrict__ xr,
                                          const float* __restrict__ xi,
                                          float* __restrict__ yr,
                                          float* __restrict__ yi,
                                          int i, int st,
                                          const float* __restrict__ Wre,
                                          const float* __restrict__ Wim)
{
    const int s = 1 << st;
    const int widx = i & ~(s - 1);
    const float wr = Wre[widx], wi = Wim[widx];
    const float ar = xr[i],       ai = xi[i];
    const float br = xr[i + 256], bi = xi[i + 256];
    const int a0 = i + widx;
    const float dr = ar - br, di = ai - bi;
    yr[a0]     = ar + br;
    yi[a0]     = ai + bi;
    yr[a0 + s] = dr * wr - di * wi;
    yi[a0 + s] = dr * wi + di * wr;
}

__global__ void __launch_bounds__(NTHREADS, 2)
poly_sketch_kernel(const float* __restrict__ X, float* __restrict__ out)
{
    extern __shared__ char sm[];
    unsigned short* shPerm = (unsigned short*)(sm + OFF_PERM);
    unsigned short* shOff  = (unsigned short*)(sm + OFF_OFF);
    float2* shX2 = (float2*)(sm + OFF_X2);
    float* reA = (float*)(sm + OFF_REA);
    float* imA = (float*)(sm + OFF_IMA);
    float* reB = (float*)(sm + OFF_REB);
    float* imB = (float*)(sm + OFF_IMB);
    float* S2  = (float*)(sm + OFF_S2);
    float* Tre = (float*)(sm + OFF_T);            // [2][257]
    float* Tim = Tre + 2 * 257;
    float* Pre = (float*)(sm + OFF_P);            // [4][257]
    float* Pim = Pre + 4 * 257;
    float* Wre = (float*)(sm + OFF_W);
    float* Wim = Wre + 256;

    const int tid = threadIdx.x;

    // ---- load CSR (int loads) + twiddles ----
    {
        const int* gp = (const int*)g_perm;
        int* sp = (int*)shPerm;
        #pragma unroll
        for (int i = tid; i < DEG * PSTRIDE / 2; i += NTHREADS)
            sp[i] = gp[i];
        for (int i = tid; i < DEG * (NB + 1); i += NTHREADS)
            shOff[i] = g_off[i];
    }
    if (tid < 256) {
        float ang = -6.283185307179586f * (float)tid * (1.0f / 512.0f);
        float s, c; sincosf(ang, &s, &c);
        Wre[tid] = c; Wim[tid] = s;
    }
    if (tid == 0) shX2[4096] = make_float2(0.f, 0.f);   // pad-entry zero slot
    __syncthreads();

    const int row0 = blockIdx.x * ROWS_PER_CTA;

    for (int g = 0; g < ROWS_PER_CTA / 4; g++) {
        const int grow = row0 + g * 4;

        for (int p = 0; p < 2; p++) {
            const int r0 = grow + 2 * p;
            const int r1 = r0 + 1;

            // ---- stage X pair, interleaved float2 ----
            {
                const float2* X0 = (const float2*)(X + (size_t)r0 * FDIM);
                const float2* X1 = (const float2*)(X + (size_t)r1 * FDIM);
                #pragma unroll
                for (int j = 0; j < (FDIM / 2) / NTHREADS; j++) {
                    int f2 = j * NTHREADS + tid;
                    float2 v0 = X0[f2];
                    float2 v1 = X1[f2];
                    shX2[2 * f2]     = make_float2(v0.x, v1.x);
                    shX2[2 * f2 + 1] = make_float2(v0.y, v1.y);
                }
            }
            __syncthreads();

            // ---- gather count-sketch, both rows, 3 degrees ----
            {
                #pragma unroll
                for (int d = 0; d < DEG; d++) {
                    const unsigned* pm = (const unsigned*)shPerm + d * (PSTRIDE / 2);
                    int s = shOff[d * (NB + 1) + tid];
                    int e = shOff[d * (NB + 1) + tid + 1];
                    float a0 = 0.f, a1 = 0.f;
                    for (int q = s; q < e; q++) {
                        unsigned w = pm[q];
                        unsigned e0 = w & 0xffffu, e1 = w >> 16;
                        float2 x0 = shX2[e0 & 0x1fffu];
                        unsigned m0 = ((~e0) & 0x8000u) << 16;
                        a0 += __int_as_float(__float_as_int(x0.x) ^ m0);
                        a1 += __int_as_float(__float_as_int(x0.y) ^ m0);
                        float2 x1 = shX2[e1 & 0x1fffu];
                        unsigned m1 = ((~e1) & 0x8000u) << 16;
                        a0 += __int_as_float(__float_as_int(x1.x) ^ m1);
                        a1 += __int_as_float(__float_as_int(x1.y) ^ m1);
                    }
                    if (d == 0)      { reA[tid] = a0; imA[tid] = a1; }
                    else if (d == 1) { reB[tid] = a0; imB[tid] = a1; }
                    else             { S2[tid] = a0;  S2[NB + tid] = a1; }
                }
            }
            __syncthreads();

            // ---- wave 1: FFT(d0 pair) on A, FFT(d1 pair) on B ----
            {
                const int i = tid & 255;
                float* sre = (tid < 256) ? reA : reB;
                float* sim = (tid < 256) ? imA : imB;
                #pragma unroll
                for (int st = 0; st < 9; st++) {
                    const int src = st & 1;
                    fft_stage(sre + src * NB, sim + src * NB,
                              sre + (src ^ 1) * NB, sim + (src ^ 1) * NB,
                              i, st, Wre, Wim);
                    __syncthreads();
                }
            }

            // ---- split + partial product T(r) = S_d0(r) * S_d1(r) ----
            if (tid <= 256) {
                const int k = tid;
                const int kr = (NB - k) & (NB - 1);
                float x = reA[NB + k],  y = imA[NB + k];
                float u = reA[NB + kr], v = imA[NB + kr];
                float a0r = 0.5f * (x + u), a0i = 0.5f * (y - v);   // S_d0(r0)
                float b0r = 0.5f * (y + v), b0i = 0.5f * (u - x);   // S_d0(r1)
                x = reB[NB + k];  y = imB[NB + k];
                u = reB[NB + kr]; v = imB[NB + kr];
                float a1r = 0.5f * (x + u), a1i = 0.5f * (y - v);   // S_d1(r0)
                float b1r = 0.5f * (y + v), b1i = 0.5f * (u - x);   // S_d1(r1)
                Tre[k]       = a0r * a1r - a0i * a1i;
                Tim[k]       = a0r * a1i + a0i * a1r;
                Tre[257 + k] = b0r * b1r - b0i * b1i;
                Tim[257 + k] = b0r * b1i + b0i * b1r;
            }
            __syncthreads();

            // ---- wave 2: FFT(d2 pair), stage0 reads S2 stash, slot A ----
            #pragma unroll
            for (int st = 0; st < 9; st++) {
                if (tid < 256) {
                    const float *xr, *xi; float *yr, *yi;
                    if (st == 0) { xr = S2; xi = S2 + NB; yr = reA + NB; yi = imA + NB; }
                    else {
                        int s = st & 1;
                        xr = reA + s * NB;        xi = imA + s * NB;
                        yr = reA + (s ^ 1) * NB;  yi = imA + (s ^ 1) * NB;
                    }
                    fft_stage(xr, xi, yr, yi, tid, st, Wre, Wim);
                }
                __syncthreads();
            }

            // ---- split d2 + final product -> P rows 2p, 2p+1 ----
            if (tid <= 256) {
                const int k = tid;
                const int kr = (NB - k) & (NB - 1);
                float x = reA[NB + k],  y = imA[NB + k];
                float u = reA[NB + kr], v = imA[NB + kr];
                float a2r = 0.5f * (x + u), a2i = 0.5f * (y - v);   // S_d2(r0)
                float b2r = 0.5f * (y + v), b2i = 0.5f * (u - x);   // S_d2(r1)
                float t0r = Tre[k], t0i = Tim[k];
                float t1r = Tre[257 + k], t1i = Tim[257 + k];
                Pre[(2 * p) * 257 + k]     = t0r * a2r - t0i * a2i;
                Pim[(2 * p) * 257 + k]     = t0r * a2i + t0i * a2r;
                Pre[(2 * p + 1) * 257 + k] = t1r * b2r - t1i * b2i;
                Pim[(2 * p + 1) * 257 + k] = t1r * b2i + t1i * b2r;
            }
            __syncthreads();
        }

        // ---- packed inverse: Q01 = conj(P0 + iP1) -> A, Q23 -> B ----
        {
            const int k = tid;
            float p0r, p0i, p1r, p1i, p2r, p2i, p3r, p3i;
            if (k <= 256) {
                p0r = Pre[k];           p0i = Pim[k];
                p1r = Pre[257 + k];     p1i = Pim[257 + k];
                p2r = Pre[2 * 257 + k]; p2i = Pim[2 * 257 + k];
                p3r = Pre[3 * 257 + k]; p3i = Pim[3 * 257 + k];
            } else {
                const int kr = NB - k;
                p0r = Pre[kr];           p0i = -Pim[kr];
                p1r = Pre[257 + kr];     p1i = -Pim[257 + kr];
                p2r = Pre[2 * 257 + kr]; p2i = -Pim[2 * 257 + kr];
                p3r = Pre[3 * 257 + kr]; p3i = -Pim[3 * 257 + kr];
            }
            reA[k] = p0r - p1i;
            imA[k] = -(p0i + p1r);
            reB[k] = p2r - p3i;
            imB[k] = -(p2i + p3r);
        }
        __syncthreads();

        {
            const int i = tid & 255;
            float* sre = (tid < 256) ? reA : reB;
            float* sim = (tid < 256) ? imA : imB;
            #pragma unroll
            for (int st = 0; st < 9; st++) {
                const int src = st & 1;
                fft_stage(sre + src * NB, sim + src * NB,
                          sre + (src ^ 1) * NB, sim + (src ^ 1) * NB,
                          i, st, Wre, Wim);
                __syncthreads();
            }
        }

        {
            const float inv = 1.0f / 512.0f;
            out[(size_t)(grow + 0) * NB + tid] =  reA[NB + tid] * inv;
            out[(size_t)(grow + 1) * NB + tid] = -imA[NB + tid] * inv;
            out[(size_t)(grow + 2) * NB + tid] =  reB[NB + tid] * inv;
            out[(size_t)(grow + 3) * NB + tid] = -imB[NB + tid] * inv;
        }
        __syncthreads();
    }
}

extern "C" void kernel_launch(void* const* d_in, const int* in_sizes, int n_in,
                              void* d_out, int out_size)
{
    const float* X  = (const float*)d_in[0];
    const int*   ih = (const int*)d_in[1];
    const int*   bh = (const int*)d_in[2];
    float* out = (float*)d_out;

    cudaFuncSetAttribute(poly_sketch_kernel,
                         cudaFuncAttributeMaxDynamicSharedMemorySize, SMEM_BYTES);
    build_csr<<<1, NTHREADS>>>(ih, bh);
    poly_sketch_kernel<<<BATCH / ROWS_PER_CTA, NTHREADS, SMEM_BYTES>>>(X, out);
}

// round 8
// speedup vs baseline: 1.3928x; 1.3928x over previous
#include <cuda_runtime.h>
#include <math.h>

#define NB 512
#define FDIM 4096
#define DEG 3
#define ROWS_PER_CTA 8
#define NTHREADS 512
#define BATCH 8192
#define PSTRIDE 4608
#define NG (ROWS_PER_CTA / 4)

// CSR of inverted hash tables (built once per launch, deterministic).
// perm entry (u16): feature(13 bits, 4096 = zero-pad slot) | sign<<15 (1 -> +x)
__device__ __align__(16) unsigned short g_perm[DEG * PSTRIDE];
__device__ __align__(16) unsigned short g_off[DEG * (NB + 1)];

// ---------------------------------------------------------------------------
// Prologue: one block per degree. 16 chunks of 256 features, chunk-major
// stable ordering, in-warp rank via __match_any.
// ---------------------------------------------------------------------------
__global__ void __launch_bounds__(NTHREADS)
build_csr(const int* __restrict__ idxh, const int* __restrict__ bith)
{
    __shared__ int hist[16][NB];
    __shared__ int tot[NB];
    __shared__ int sc[2][NB];
    const int t = threadIdx.x;
    const int d = blockIdx.x;
    const int w = t >> 5, lane = t & 31;

    for (int i = t; i < 16 * NB; i += NTHREADS) ((int*)hist)[i] = 0;
    __syncthreads();

    {   // chunk w = features [256w, 256w+256)
        const int base = d * FDIM + w * 256;
        for (int it = 0; it < 8; it++) {
            int b = idxh[base + it * 32 + lane];
            atomicAdd(&hist[w][b], 1);
        }
    }
    __syncthreads();

    // prefill pads (f=4096 -> zero slot, sign 0)
    for (int i = t; i < PSTRIDE; i += NTHREADS) g_perm[d * PSTRIDE + i] = 0x1000;

    {   // totals, padded to even
        int c = 0;
        #pragma unroll
        for (int ch = 0; ch < 16; ch++) c += hist[ch][t];
        tot[t] = c + (c & 1);
    }
    __syncthreads();
    int* s = sc[0]; int* dd = sc[1];
    s[t] = tot[t]; __syncthreads();
    for (int off = 1; off < NB; off <<= 1) {
        int v = s[t];
        if (t >= off) v += s[t - off];
        dd[t] = v;
        int* tmp = s; s = dd; dd = tmp;
        __syncthreads();
    }
    const int excl = (t == 0) ? 0 : s[t - 1];
    g_off[d * (NB + 1) + t] = (unsigned short)(excl >> 1);
    if (t == NB - 1) g_off[d * (NB + 1) + NB] = (unsigned short)(s[NB - 1] >> 1);
    {   // per-chunk cursors
        int base = excl;
        #pragma unroll
        for (int c = 0; c < 16; c++) {
            int h = hist[c][t];
            hist[c][t] = base;
            base += h;
        }
    }
    __syncthreads();

    {   // stable scatter, chunk w
        const int fbase = w * 256;
        for (int it = 0; it < 8; it++) {
            int f  = fbase + it * 32 + lane;
            int b  = idxh[d * FDIM + f];
            int sg = bith[d * FDIM + f];
            unsigned m = __match_any_sync(0xffffffffu, b);
            int rank = __popc(m & ((1u << lane) - 1));
            int grp  = __popc(m);
            int base = hist[w][b];
            g_perm[d * PSTRIDE + base + rank] = (unsigned short)(f | (sg << 15));
            if (rank == grp - 1) hist[w][b] = base + grp;
            __syncwarp();
        }
    }
}

// ---------------------------------------------------------------------------
// Radix-8 Stockham stage. S = stride (1, 8, 64). MI/MO = swizzle mode of
// input/output buffer: 0 = natural, 1 = phiA(m)=m^((m>>5)&7),
// 2 = phiB(m)=m^(((m>>6)&3)<<3). All load/store patterns conflict-free.
// ---------------------------------------------------------------------------
__device__ __forceinline__ int swzf(int m, int mode) {
    if (mode == 1) return m ^ ((m >> 5) & 7);
    if (mode == 2) return m ^ (((m >> 6) & 3) << 3);
    return m;
}

template<int S, int MI, int MO>
__device__ __forceinline__ void r8_stage(const float* __restrict__ xr,
                                         const float* __restrict__ xi,
                                         float* __restrict__ yr,
                                         float* __restrict__ yi,
                                         int t,
                                         const float* __restrict__ Wre,
                                         const float* __restrict__ Wim)
{
    const int p = t / S;
    const int q = t - p * S;
    float ar[8], ai[8];
    #pragma unroll
    for (int j = 0; j < 8; j++) {
        const int m = swzf(t + 64 * j, MI);
        ar[j] = xr[m];
        ai[j] = xi[m];
    }
    // layer 1
    float b0r=ar[0]+ar[4], b0i=ai[0]+ai[4];
    float b4r=ar[0]-ar[4], b4i=ai[0]-ai[4];
    float b1r=ar[1]+ar[5], b1i=ai[1]+ai[5];
    float b5r=ar[1]-ar[5], b5i=ai[1]-ai[5];
    float b2r=ar[2]+ar[6], b2i=ai[2]+ai[6];
    float b6r=ar[2]-ar[6], b6i=ai[2]-ai[6];
    float b3r=ar[3]+ar[7], b3i=ai[3]+ai[7];
    float b7r=ar[3]-ar[7], b7i=ai[3]-ai[7];
    // layer 2 ( -i*z = (z.im, -z.re) )
    float c0r=b0r+b2r, c0i=b0i+b2i;
    float c2r=b0r-b2r, c2i=b0i-b2i;
    float c1r=b1r+b3r, c1i=b1i+b3i;
    float c3r=b1r-b3r, c3i=b1i-b3i;
    float c4r=b4r+b6i, c4i=b4i-b6r;
    float c6r=b4r-b6i, c6i=b4i+b6r;
    float c5r=b5r+b7i, c5i=b5i-b7r;
    float c7r=b5r-b7i, c7i=b5i+b7r;
    // layer 3
    float Xr[8], Xi[8];
    Xr[0]=c0r+c1r; Xi[0]=c0i+c1i;
    Xr[4]=c0r-c1r; Xi[4]=c0i-c1i;
    Xr[2]=c2r+c3i; Xi[2]=c2i-c3r;
    Xr[6]=c2r-c3i; Xi[6]=c2i+c3r;
    const float R2 = 0.70710678118654752440f;
    const float u5r=(c5r+c5i)*R2, u5i=(c5i-c5r)*R2;        // w8^1 * c5
    Xr[1]=c4r+u5r; Xi[1]=c4i+u5i;
    Xr[5]=c4r-u5r; Xi[5]=c4i-u5i;
    const float u7r=(c7i-c7r)*R2, u7i=-(c7r+c7i)*R2;       // w8^3 * c7
    Xr[3]=c6r+u7r; Xi[3]=c6i+u7i;
    Xr[7]=c6r-u7r; Xi[7]=c6i-u7i;

    if (S < 64) {   // twiddle chain from single table lookup W^{S*p}
        const int e = S * p;
        const float w1r = Wre[e], w1i = Wim[e];
        float wr = w1r, wi = w1i;
        #pragma unroll
        for (int k = 1; k < 8; k++) {
            const float tr = Xr[k]*wr - Xi[k]*wi;
            const float ti = Xr[k]*wi + Xi[k]*wr;
            Xr[k] = tr; Xi[k] = ti;
            const float nr = wr*w1r - wi*w1i;
            const float ni = wr*w1i + wi*w1r;
            wr = nr; wi = ni;
        }
    }
    #pragma unroll
    for (int k = 0; k < 8; k++) {
        const int m = swzf(8*S*p + q + S*k, MO);
        yr[m] = Xr[k];
        yi[m] = Xi[k];
    }
}

// ---------------------------------------------------------------------------
// Main kernel (pipelined):
//  gi-th iteration: stage+gather group gi (fwd inputs, buf0 slots 0-5),
//  prep inverse inputs of group gi-1 (slots 6-7), ONE 8-slot radix-8 wave
//  (3 stages, named barriers per slot), then products -> P[gi&1] and
//  output writeback of group gi-1.
// ---------------------------------------------------------------------------
#define OFF_PERM   0          // 27648 (3*4608 u16)
#define OFF_OFF    27648      // 3078 -> 3080
#define OFF_X      30728      // 32776 (4097 float2); buf1 aliases first 32768
#define OFF_BUF0   63504      // 32768 (re[8][512], im[8][512])
#define OFF_P      96272      // 16448: Pre[2][1028] | Pim[2][1028]
#define OFF_W      112720     // 2048
#define SMEM_BYTES 114768

__global__ void __launch_bounds__(NTHREADS, 2)
poly_sketch_kernel(const float* __restrict__ X, float* __restrict__ out)
{
    extern __shared__ char sm[];
    unsigned short* shPerm = (unsigned short*)(sm + OFF_PERM);
    unsigned short* shOff  = (unsigned short*)(sm + OFF_OFF);
    float2* shX2 = (float2*)(sm + OFF_X);
    float*  buf1 = (float*)(sm + OFF_X);       // aliases shX2 (disjoint lifetime)
    float*  buf0 = (float*)(sm + OFF_BUF0);
    float*  Pre  = (float*)(sm + OFF_P);
    float*  Pim  = Pre + 2 * 1028;
    float*  Wre  = (float*)(sm + OFF_W);
    float*  Wim  = Wre + 256;

    const int tid = threadIdx.x;

    {   // load CSR
        const int* gp = (const int*)g_perm;
        int* sp = (int*)shPerm;
        #pragma unroll
        for (int i = tid; i < DEG * PSTRIDE / 2; i += NTHREADS) sp[i] = gp[i];
        for (int i = tid; i < DEG * (NB + 1); i += NTHREADS) shOff[i] = g_off[i];
    }
    if (tid < 256) {
        float ang = -6.283185307179586f * (float)tid * (1.0f / 512.0f);
        float s, c; sincosf(ang, &s, &c);
        Wre[tid] = c; Wim[tid] = s;
    }
    if (tid == 0) shX2[4096] = make_float2(0.f, 0.f);  // pad slot (never clobbered)
    __syncthreads();

    const int row0 = blockIdx.x * ROWS_PER_CTA;
    const int fftid = tid >> 6;
    const int t64 = tid & 63;

    for (int gi = 0; gi <= NG; gi++) {
        if (gi < NG) {
            const int grow = row0 + gi * 4;
            #pragma unroll
            for (int pp = 0; pp < 2; pp++) {
                const int r0 = grow + 2 * pp;
                {   // stage X pair, interleaved float2, swizzled (conflict-free)
                    const float4* X0 = (const float4*)(X + (size_t)r0 * FDIM);
                    const float4* X1 = (const float4*)(X + (size_t)(r0 + 1) * FDIM);
                    #pragma unroll
                    for (int j = 0; j < (FDIM / 4) / NTHREADS; j++) {
                        const int f4 = j * NTHREADS + tid;
                        const float4 v0 = X0[f4];
                        const float4 v1 = X1[f4];
                        const int sidx = 4 * f4;
                        const int wz = (f4 >> 2) & 3;
                        shX2[sidx + (0 ^ wz)] = make_float2(v0.x, v1.x);
                        shX2[sidx + (1 ^ wz)] = make_float2(v0.y, v1.y);
                        shX2[sidx + (2 ^ wz)] = make_float2(v0.z, v1.z);
                        shX2[sidx + (3 ^ wz)] = make_float2(v0.w, v1.w);
                    }
                }
                __syncthreads();
                // gather count-sketch, both rows, 3 degrees -> buf0 slots 3pp+d
                #pragma unroll
                for (int d = 0; d < DEG; d++) {
                    const unsigned* pm = (const unsigned*)shPerm + d * (PSTRIDE / 2);
                    const int s = shOff[d * (NB + 1) + tid];
                    const int e = shOff[d * (NB + 1) + tid + 1];
                    float a0 = 0.f, a1 = 0.f;
                    for (int qq = s; qq < e; qq++) {
                        const unsigned w = pm[qq];
                        const unsigned e0 = w & 0xffffu, e1 = w >> 16;
                        int s0 = e0 & 0x1fffu; s0 ^= (s0 >> 4) & 3;
                        const float2 x0 = shX2[s0];
                        const unsigned m0 = ((~e0) & 0x8000u) << 16;
                        a0 += __int_as_float(__float_as_int(x0.x) ^ m0);
                        a1 += __int_as_float(__float_as_int(x0.y) ^ m0);
                        int s1 = e1 & 0x1fffu; s1 ^= (s1 >> 4) & 3;
                        const float2 x1 = shX2[s1];
                        const unsigned m1 = ((~e1) & 0x8000u) << 16;
                        a0 += __int_as_float(__float_as_int(x1.x) ^ m1);
                        a1 += __int_as_float(__float_as_int(x1.y) ^ m1);
                    }
                    const int slot = pp * 3 + d;
                    buf0[slot * 512 + tid]        = a0;  // row r0 (real)
                    buf0[4096 + slot * 512 + tid] = a1;  // row r0+1 (imag)
                }
                __syncthreads();
            }
        }

        if (gi > 0) {   // prep inverse inputs Q from P[(gi-1)&1] -> slots 6,7
            const int pb = (gi - 1) & 1;
            const float* Pr = Pre + pb * 1028;
            const float* Pi = Pim + pb * 1028;
            const int k = tid;
            float p0r, p0i, p1r, p1i, p2r, p2i, p3r, p3i;
            if (k <= 256) {
                p0r = Pr[k];        p0i = Pi[k];
                p1r = Pr[257 + k];  p1i = Pi[257 + k];
                p2r = Pr[514 + k];  p2i = Pi[514 + k];
                p3r = Pr[771 + k];  p3i = Pi[771 + k];
            } else {
                const int kr = NB - k;
                p0r = Pr[kr];        p0i = -Pi[kr];
                p1r = Pr[257 + kr];  p1i = -Pi[257 + kr];
                p2r = Pr[514 + kr];  p2i = -Pi[514 + kr];
                p3r = Pr[771 + kr];  p3i = -Pi[771 + kr];
            }
            buf0[6 * 512 + k]        = p0r - p1i;     // Re(conj(P0 + iP1))
            buf0[4096 + 6 * 512 + k] = -(p0i + p1r);  // Im
            buf0[7 * 512 + k]        = p2r - p3i;
            buf0[4096 + 7 * 512 + k] = -(p2i + p3r);
        }
        __syncthreads();

        {   // 8-slot radix-8 FFT wave, named barrier per slot between stages
            const bool active = (fftid < 6) ? (gi < NG) : (gi > 0);
            if (active) {
                float* b0r = buf0 + fftid * 512;
                float* b0i = buf0 + 4096 + fftid * 512;
                float* b1r = buf1 + fftid * 512;
                float* b1i = buf1 + 4096 + fftid * 512;
                r8_stage<1, 0, 1>(b0r, b0i, b1r, b1i, t64, Wre, Wim);
                asm volatile("bar.sync %0, 64;" :: "r"(fftid + 1) : "memory");
                r8_stage<8, 1, 2>(b1r, b1i, b0r, b0i, t64, Wre, Wim);
                asm volatile("bar.sync %0, 64;" :: "r"(fftid + 1) : "memory");
                r8_stage<64, 2, 0>(b0r, b0i, b1r, b1i, t64, Wre, Wim);
            }
        }
        __syncthreads();

        if (gi < NG) {  // Hermitian split + 3-way spectral product -> P[gi&1]
            const int pb = gi & 1;
            const int pp = tid >> 8;
            const int k0 = tid & 255;
            const int nrep = (k0 == 0) ? 2 : 1;   // thread k0==0 also does k=256
            for (int rep = 0; rep < nrep; rep++) {
                const int k = rep ? 256 : k0;
                const int kr = (NB - k) & (NB - 1);
                float er = 1.f, ei = 0.f, odr = 1.f, odi = 0.f;
                #pragma unroll
                for (int d = 0; d < DEG; d++) {
                    const int slot = pp * 3 + d;
                    const float x = buf1[slot * 512 + k];
                    const float y = buf1[4096 + slot * 512 + k];
                    const float u = buf1[slot * 512 + kr];
                    const float v = buf1[4096 + slot * 512 + kr];
                    const float ser = 0.5f * (x + u), sei = 0.5f * (y - v);
                    const float sor = 0.5f * (y + v), soi = 0.5f * (u - x);
                    float tr = er * ser - ei * sei;  ei = er * sei + ei * ser;  er = tr;
                    tr = odr * sor - odi * soi;      odi = odr * soi + odi * sor; odr = tr;
                }
                Pre[pb * 1028 + (2 * pp) * 257 + k]     = er;
                Pim[pb * 1028 + (2 * pp) * 257 + k]     = ei;
                Pre[pb * 1028 + (2 * pp + 1) * 257 + k] = odr;
                Pim[pb * 1028 + (2 * pp + 1) * 257 + k] = odi;
            }
        }
        if (gi > 0) {   // output writeback of group gi-1 from slots 6,7
            const float inv = 1.0f / 512.0f;
            const int orow = row0 + (gi - 1) * 4;
            out[(size_t)(orow + 0) * NB + tid] =  buf1[6 * 512 + tid] * inv;
            out[(size_t)(orow + 1) * NB + tid] = -buf1[4096 + 6 * 512 + tid] * inv;
            out[(size_t)(orow + 2) * NB + tid] =  buf1[7 * 512 + tid] * inv;
            out[(size_t)(orow + 3) * NB + tid] = -buf1[4096 + 7 * 512 + tid] * inv;
        }
        __syncthreads();
    }
}

extern "C" void kernel_launch(void* const* d_in, const int* in_sizes, int n_in,
                              void* d_out, int out_size)
{
    const float* X  = (const float*)d_in[0];
    const int*   ih = (const int*)d_in[1];
    const int*   bh = (const int*)d_in[2];
    float* out = (float*)d_out;

    cudaFuncSetAttribute(poly_sketch_kernel,
                         cudaFuncAttributeMaxDynamicSharedMemorySize, SMEM_BYTES);
    build_csr<<<DEG, NTHREADS>>>(ih, bh);
    poly_sketch_kernel<<<BATCH / ROWS_PER_CTA, NTHREADS, SMEM_BYTES>>>(X, out);
}

// round 9
// speedup vs baseline: 1.4750x; 1.0590x over previous
#include <cuda_runtime.h>
#include <math.h>

#define NB 512
#define FDIM 4096
#define DEG 3
#define NTHREADS 512
#define BATCH 8192
#define PSTRIDE 4608
#define NGROUPS (BATCH / 4)      // 2048 groups of 4 rows
#define GRID_MAIN 296            // 148 SMs x 2 CTAs

// CSR of inverted hash tables (built once per launch, deterministic).
// perm entry (u16): PRE-SWIZZLED feature (13 bits; swizzle f^((f>>4)&3),
// 4096 = zero-pad slot) | sign<<15 (1 -> +x)
__device__ __align__(16) unsigned short g_perm[DEG * PSTRIDE];
__device__ __align__(16) unsigned short g_off[DEG * (NB + 1)];
__device__ unsigned g_ctr;

// ---------------------------------------------------------------------------
// Prologue: one block per degree. 16 chunks of 256 features, chunk-major
// stable ordering, in-warp rank via __match_any. Also resets work counter.
// ---------------------------------------------------------------------------
__global__ void __launch_bounds__(NTHREADS)
build_csr(const int* __restrict__ idxh, const int* __restrict__ bith)
{
    __shared__ int hist[16][NB];
    __shared__ int tot[NB];
    __shared__ int sc[2][NB];
    const int t = threadIdx.x;
    const int d = blockIdx.x;
    const int w = t >> 5, lane = t & 31;

    if (d == 0 && t == 0) g_ctr = 0;    // reset persistent-work counter

    for (int i = t; i < 16 * NB; i += NTHREADS) ((int*)hist)[i] = 0;
    __syncthreads();

    {   // chunk w = features [256w, 256w+256)
        const int base = d * FDIM + w * 256;
        for (int it = 0; it < 8; it++) {
            int b = idxh[base + it * 32 + lane];
            atomicAdd(&hist[w][b], 1);
        }
    }
    __syncthreads();

    // prefill pads (f=4096 -> zero slot, sign 0)
    for (int i = t; i < PSTRIDE; i += NTHREADS) g_perm[d * PSTRIDE + i] = 0x1000;

    {   // totals, padded to even
        int c = 0;
        #pragma unroll
        for (int ch = 0; ch < 16; ch++) c += hist[ch][t];
        tot[t] = c + (c & 1);
    }
    __syncthreads();
    int* s = sc[0]; int* dd = sc[1];
    s[t] = tot[t]; __syncthreads();
    for (int off = 1; off < NB; off <<= 1) {
        int v = s[t];
        if (t >= off) v += s[t - off];
        dd[t] = v;
        int* tmp = s; s = dd; dd = tmp;
        __syncthreads();
    }
    const int excl = (t == 0) ? 0 : s[t - 1];
    g_off[d * (NB + 1) + t] = (unsigned short)(excl >> 1);
    if (t == NB - 1) g_off[d * (NB + 1) + NB] = (unsigned short)(s[NB - 1] >> 1);
    {   // per-chunk cursors
        int base = excl;
        #pragma unroll
        for (int c = 0; c < 16; c++) {
            int h = hist[c][t];
            hist[c][t] = base;
            base += h;
        }
    }
    __syncthreads();

    {   // stable scatter, chunk w; store PRE-SWIZZLED feature index
        const int fbase = w * 256;
        for (int it = 0; it < 8; it++) {
            int f  = fbase + it * 32 + lane;
            int b  = idxh[d * FDIM + f];
            int sg = bith[d * FDIM + f];
            int fs = f ^ ((f >> 4) & 3);          // staging swizzle (bits 0-1)
            unsigned m = __match_any_sync(0xffffffffu, b);
            int rank = __popc(m & ((1u << lane) - 1));
            int grp  = __popc(m);
            int base = hist[w][b];
            g_perm[d * PSTRIDE + base + rank] = (unsigned short)(fs | (sg << 15));
            if (rank == grp - 1) hist[w][b] = base + grp;
            __syncwarp();
        }
    }
}

// ---------------------------------------------------------------------------
// float2 (complex) radix-8 Stockham stage. Swizzle for 64-bit bank pattern:
// phi(m) = m ^ (((m>>4)&7) | (((m>>6)&1)<<3)) — conflict-free for all
// load (t+64j) and store (8t+k / 64p+q+8k / t+64k) patterns at bank16.
// ---------------------------------------------------------------------------
__device__ __forceinline__ int phi(int m) {
    return m ^ (((m >> 4) & 7) | (((m >> 6) & 1) << 3));
}

template<int S, int MI, int MO>
__device__ __forceinline__ void r8c_stage(const float2* __restrict__ x,
                                          float2* __restrict__ y,
                                          int t, const float2* __restrict__ Wc)
{
    const int p = t / S;
    const int q = t - p * S;
    float ar[8], ai[8];
    #pragma unroll
    for (int j = 0; j < 8; j++) {
        int m = t + 64 * j;
        if (MI) m = phi(m);
        const float2 v = x[m];
        ar[j] = v.x; ai[j] = v.y;
    }
    // layer 1
    float b0r=ar[0]+ar[4], b0i=ai[0]+ai[4];
    float b4r=ar[0]-ar[4], b4i=ai[0]-ai[4];
    float b1r=ar[1]+ar[5], b1i=ai[1]+ai[5];
    float b5r=ar[1]-ar[5], b5i=ai[1]-ai[5];
    float b2r=ar[2]+ar[6], b2i=ai[2]+ai[6];
    float b6r=ar[2]-ar[6], b6i=ai[2]-ai[6];
    float b3r=ar[3]+ar[7], b3i=ai[3]+ai[7];
    float b7r=ar[3]-ar[7], b7i=ai[3]-ai[7];
    // layer 2 ( -i*z = (z.im, -z.re) )
    float c0r=b0r+b2r, c0i=b0i+b2i;
    float c2r=b0r-b2r, c2i=b0i-b2i;
    float c1r=b1r+b3r, c1i=b1i+b3i;
    float c3r=b1r-b3r, c3i=b1i-b3i;
    float c4r=b4r+b6i, c4i=b4i-b6r;
    float c6r=b4r-b6i, c6i=b4i+b6r;
    float c5r=b5r+b7i, c5i=b5i-b7r;
    float c7r=b5r-b7i, c7i=b5i+b7r;
    // layer 3
    float Xr[8], Xi[8];
    Xr[0]=c0r+c1r; Xi[0]=c0i+c1i;
    Xr[4]=c0r-c1r; Xi[4]=c0i-c1i;
    Xr[2]=c2r+c3i; Xi[2]=c2i-c3r;
    Xr[6]=c2r-c3i; Xi[6]=c2i+c3r;
    const float R2 = 0.70710678118654752440f;
    const float u5r=(c5r+c5i)*R2, u5i=(c5i-c5r)*R2;        // w8^1 * c5
    Xr[1]=c4r+u5r; Xi[1]=c4i+u5i;
    Xr[5]=c4r-u5r; Xi[5]=c4i-u5i;
    const float u7r=(c7i-c7r)*R2, u7i=-(c7r+c7i)*R2;       // w8^3 * c7
    Xr[3]=c6r+u7r; Xi[3]=c6i+u7i;
    Xr[7]=c6r-u7r; Xi[7]=c6i-u7i;

    if (S < 64) {   // twiddle chain from single table lookup W^{S*p} (e<=63)
        const float2 w1 = Wc[S * p];
        float wr = w1.x, wi = w1.y;
        #pragma unroll
        for (int k = 1; k < 8; k++) {
            const float tr = Xr[k]*wr - Xi[k]*wi;
            const float ti = Xr[k]*wi + Xi[k]*wr;
            Xr[k] = tr; Xi[k] = ti;
            const float nr = wr*w1.x - wi*w1.y;
            const float ni = wr*w1.y + wi*w1.x;
            wr = nr; wi = ni;
        }
    }
    #pragma unroll
    for (int k = 0; k < 8; k++) {
        int m = 8*S*p + q + S*k;
        if (MO) m = phi(m);
        y[m] = make_float2(Xr[k], Xi[k]);
    }
}

// ---------------------------------------------------------------------------
// Persistent main kernel. Per fetched group (4 rows): stage+gather (fwd
// inputs, cbuf0 slots 0-5), prep inverse of previous group (slots 6-7),
// one 8-slot radix-8 wave (named barriers per slot), spectral product -> Pc,
// writeback of previous group.
// ---------------------------------------------------------------------------
#define OFF_PERM   0          // 27648 (3*4608 u16)
#define OFF_OFF    27648      // 3078 -> 3080
#define OFF_X      30728      // 32776 (4097 float2); cbuf1 aliases first 32768
#define OFF_BUF0   63504      // 32768 (float2[8][512])
#define OFF_P      96272      // 8224: float2[4*257]
#define OFF_W      104496     // 512: float2[64]
#define SMEM_BYTES 105008

__global__ void __launch_bounds__(NTHREADS, 2)
poly_sketch_kernel(const float* __restrict__ X, float* __restrict__ out)
{
    extern __shared__ char sm[];
    unsigned short* shPerm = (unsigned short*)(sm + OFF_PERM);
    unsigned short* shOff  = (unsigned short*)(sm + OFF_OFF);
    float2* shX2  = (float2*)(sm + OFF_X);
    float2* cbuf1 = (float2*)(sm + OFF_X);      // aliases shX2 (disjoint lifetime)
    float2* cbuf0 = (float2*)(sm + OFF_BUF0);
    float2* Pc    = (float2*)(sm + OFF_P);
    float2* Wc    = (float2*)(sm + OFF_W);
    __shared__ int sh_g;

    const int tid = threadIdx.x;

    {   // load CSR
        const int* gp = (const int*)g_perm;
        int* sp = (int*)shPerm;
        #pragma unroll
        for (int i = tid; i < DEG * PSTRIDE / 2; i += NTHREADS) sp[i] = gp[i];
        for (int i = tid; i < DEG * (NB + 1); i += NTHREADS) shOff[i] = g_off[i];
    }
    if (tid < 64) {
        float ang = -6.283185307179586f * (float)tid * (1.0f / 512.0f);
        float s, c; sincosf(ang, &s, &c);
        Wc[tid] = make_float2(c, s);
    }
    if (tid == 0) shX2[4096] = make_float2(0.f, 0.f);  // pad slot
    __syncthreads();

    const int fftid = tid >> 6;
    const int t64 = tid & 63;
    int prev = -1;

    for (;;) {
        if (tid == 0) sh_g = (int)atomicAdd(&g_ctr, 1u);
        __syncthreads();
        const int g = sh_g;
        const bool have = (g < NGROUPS);
        if (!have && prev < 0) break;

        if (have) {
            const int grow = g * 4;
            #pragma unroll
            for (int pp = 0; pp < 2; pp++) {
                const int r0 = grow + 2 * pp;
                {   // stage X pair, interleaved float2, swizzled (conflict-free)
                    const float4* X0 = (const float4*)(X + (size_t)r0 * FDIM);
                    const float4* X1 = (const float4*)(X + (size_t)(r0 + 1) * FDIM);
                    #pragma unroll
                    for (int j = 0; j < (FDIM / 4) / NTHREADS; j++) {
                        const int f4 = j * NTHREADS + tid;
                        const float4 v0 = X0[f4];
                        const float4 v1 = X1[f4];
                        const int sidx = 4 * f4;
                        const int wz = (f4 >> 2) & 3;
                        shX2[sidx + (0 ^ wz)] = make_float2(v0.x, v1.x);
                        shX2[sidx + (1 ^ wz)] = make_float2(v0.y, v1.y);
                        shX2[sidx + (2 ^ wz)] = make_float2(v0.z, v1.z);
                        shX2[sidx + (3 ^ wz)] = make_float2(v0.w, v1.w);
                    }
                }
                __syncthreads();
                // gather count-sketch, both rows, 3 degrees -> cbuf0 slots 3pp+d
                #pragma unroll
                for (int d = 0; d < DEG; d++) {
                    const unsigned* pm = (const unsigned*)shPerm + d * (PSTRIDE / 2);
                    const int s = shOff[d * (NB + 1) + tid];
                    const int e = shOff[d * (NB + 1) + tid + 1];
                    float a0 = 0.f, a1 = 0.f;
                    for (int qq = s; qq < e; qq++) {
                        const unsigned w = pm[qq];
                        const unsigned e0 = w & 0xffffu, e1 = w >> 16;
                        const float2 x0 = shX2[e0 & 0x1fffu];   // pre-swizzled
                        const unsigned m0 = ((~e0) & 0x8000u) << 16;
                        a0 += __int_as_float(__float_as_int(x0.x) ^ m0);
                        a1 += __int_as_float(__float_as_int(x0.y) ^ m0);
                        const float2 x1 = shX2[e1 & 0x1fffu];
                        const unsigned m1 = ((~e1) & 0x8000u) << 16;
                        a0 += __int_as_float(__float_as_int(x1.x) ^ m1);
                        a1 += __int_as_float(__float_as_int(x1.y) ^ m1);
                    }
                    cbuf0[(pp * 3 + d) * 512 + tid] = make_float2(a0, a1);
                }
                __syncthreads();
            }
        }

        if (prev >= 0) {   // prep inverse inputs from Pc -> slots 6,7
            const int k = tid;
            float2 p0, p1, p2, p3;
            if (k <= 256) {
                p0 = Pc[k];       p1 = Pc[257 + k];
                p2 = Pc[514 + k]; p3 = Pc[771 + k];
            } else {
                const int kr = NB - k;
                p0 = Pc[kr];       p0.y = -p0.y;
                p1 = Pc[257 + kr]; p1.y = -p1.y;
                p2 = Pc[514 + kr]; p2.y = -p2.y;
                p3 = Pc[771 + kr]; p3.y = -p3.y;
            }
            cbuf0[6 * 512 + k] = make_float2(p0.x - p1.y, -(p0.y + p1.x));
            cbuf0[7 * 512 + k] = make_float2(p2.x - p3.y, -(p2.y + p3.x));
        }
        __syncthreads();

        {   // 8-slot radix-8 FFT wave, named barrier per slot between stages
            const bool active = (fftid < 6) ? have : (prev >= 0);
            if (active) {
                const float2* b0 = cbuf0 + fftid * 512;
                float2*       b1 = cbuf1 + fftid * 512;
                r8c_stage<1, 0, 1>(b0, b1, t64, Wc);
                asm volatile("bar.sync %0, 64;" :: "r"(fftid + 1) : "memory");
                r8c_stage<8, 1, 1>(b1, (float2*)b0, t64, Wc);
                asm volatile("bar.sync %0, 64;" :: "r"(fftid + 1) : "memory");
                r8c_stage<64, 1, 0>(b0, b1, t64, Wc);
            }
        }
        __syncthreads();

        if (have) {  // Hermitian split + 3-way spectral product -> Pc
            const int pp = tid >> 8;
            const int k0 = tid & 255;
            const int nrep = (k0 == 0) ? 2 : 1;   // k0==0 also does k=256
            for (int rep = 0; rep < nrep; rep++) {
                const int k = rep ? 256 : k0;
                const int kr = (NB - k) & (NB - 1);
                float er = 1.f, ei = 0.f, odr = 1.f, odi = 0.f;
                #pragma unroll
                for (int d = 0; d < DEG; d++) {
                    const int slot = pp * 3 + d;
                    const float2 z = cbuf1[slot * 512 + k];
                    const float2 w = cbuf1[slot * 512 + kr];
                    const float ser = 0.5f * (z.x + w.x), sei = 0.5f * (z.y - w.y);
                    const float sor = 0.5f * (z.y + w.y), soi = 0.5f * (w.x - z.x);
                    float tr = er * ser - ei * sei;  ei = er * sei + ei * ser;  er = tr;
                    tr = odr * sor - odi * soi;      odi = odr * soi + odi * sor; odr = tr;
                }
                Pc[(2 * pp) * 257 + k]     = make_float2(er, ei);
                Pc[(2 * pp + 1) * 257 + k] = make_float2(odr, odi);
            }
        }
        if (prev >= 0) {   // output writeback of previous group from slots 6,7
            const float inv = 1.0f / 512.0f;
            const int orow = prev * 4;
            const float2 v6 = cbuf1[6 * 512 + tid];
            const float2 v7 = cbuf1[7 * 512 + tid];
            out[(size_t)(orow + 0) * NB + tid] =  v6.x * inv;
            out[(size_t)(orow + 1) * NB + tid] = -v6.y * inv;
            out[(size_t)(orow + 2) * NB + tid] =  v7.x * inv;
            out[(size_t)(orow + 3) * NB + tid] = -v7.y * inv;
        }
        __syncthreads();
        prev = have ? g : -1;
    }
}

extern "C" void kernel_launch(void* const* d_in, const int* in_sizes, int n_in,
                              void* d_out, int out_size)
{
    const float* X  = (const float*)d_in[0];
    const int*   ih = (const int*)d_in[1];
    const int*   bh = (const int*)d_in[2];
    float* out = (float*)d_out;

    cudaFuncSetAttribute(poly_sketch_kernel,
                         cudaFuncAttributeMaxDynamicSharedMemorySize, SMEM_BYTES);
    build_csr<<<DEG, NTHREADS>>>(ih, bh);
    poly_sketch_kernel<<<GRID_MAIN, NTHREADS, SMEM_BYTES>>>(X, out);
}